// round 1
// baseline (speedup 1.0000x reference)
#include <cuda_runtime.h>
#include <math.h>

// ---------------- problem constants ----------------
#define NN   51200      // nodes
#define NPG  100        // nodes per graph
#define NG   512        // graphs
#define EPG  1600       // edges per graph
#define NE   819200     // edges
#define FIN  128
#define HIDD 512
#define NCLS 6
#define EPSV 1e-5f

// output layout: (logp[NG*6], pos[NG*512], gemb[NG*512], penalty[1])
#define OFF_LOGP 0
#define OFF_POS  (NG * NCLS)
#define OFF_GEMB (OFF_POS + NG * HIDD)
#define OFF_PEN  (OFF_GEMB + NG * HIDD)

// ---------------- device scratch ----------------
__device__ float g_bufA[(size_t)NN * HIDD];
__device__ float g_bufB[(size_t)NN * HIDD];
__device__ float g_dis[NN];
__device__ int   g_cnt[NN];
__device__ int   g_ptr[NN + 1];
__device__ int   g_cur[NN];
__device__ int   g_csrc[NE];
__device__ float g_assign[NN * 2];
__device__ float g_pos[NG * HIDD];
__device__ float g_adj[NG * 4];
__device__ float g_colsum[HIDD];
__device__ float g_m[HIDD];
__device__ float g_scal[4];

// ---------------- CSR build ----------------
__global__ void k_count(const int* __restrict__ dst) {
    int e = blockIdx.x * blockDim.x + threadIdx.x;
    if (e < NE) atomicAdd(&g_cnt[dst[e]], 1);
}

// one thread per graph: prefix-scan the 100 counts, compute dis
__global__ void k_scan() {
    int g = blockIdx.x * blockDim.x + threadIdx.x;
    if (g >= NG) return;
    int base = g * NPG;
    int run = g * EPG;
    for (int i = 0; i < NPG; i++) {
        int c = g_cnt[base + i];
        g_ptr[base + i] = run;
        g_cur[base + i] = run;
        g_dis[base + i] = rsqrtf((float)c + 1.0f);
        run += c;
    }
    if (g == NG - 1) g_ptr[NN] = run;
}

__global__ void k_fill(const int* __restrict__ src, const int* __restrict__ dst) {
    int e = blockIdx.x * blockDim.x + threadIdx.x;
    if (e < NE) {
        int d = dst[e];
        int p = atomicAdd(&g_cur[d], 1);
        g_csrc[p] = src[e];
    }
}

// ---------------- generic fp32 GEMM, N fixed = 512 ----------------
// C[M,512] = act(A[M,K] @ B[K,512] + bias)
#define BM 128
#define BN 128
#define BK 8
__global__ __launch_bounds__(256) void gemm512(
    const float* __restrict__ A, const float* __restrict__ B,
    const float* __restrict__ bias, float* __restrict__ C,
    int M, int K, int act)
{
    __shared__ float As[BK][BM + 4];   // padded to kill store conflicts
    __shared__ float Bs[BK][BN];

    int tid = threadIdx.x;
    int row0 = blockIdx.y * BM, col0 = blockIdx.x * BN;

    int arow = tid >> 1, ak4 = (tid & 1) * 4;      // A tile: 128 rows x 8 k
    int brow = tid >> 5, bcol = (tid & 31) * 4;    // B tile: 8 k x 128 cols
    int tx = tid & 15, ty = tid >> 4;

    float acc[8][8];
    #pragma unroll
    for (int i = 0; i < 8; i++)
        #pragma unroll
        for (int j = 0; j < 8; j++) acc[i][j] = 0.f;

    const float* Aptr = A + (size_t)(row0 + arow) * K + ak4;

    for (int k0 = 0; k0 < K; k0 += BK) {
        float4 av = *(const float4*)Aptr; Aptr += BK;
        float4 bv = *(const float4*)(B + (size_t)(k0 + brow) * HIDD + col0 + bcol);
        As[ak4 + 0][arow] = av.x;
        As[ak4 + 1][arow] = av.y;
        As[ak4 + 2][arow] = av.z;
        As[ak4 + 3][arow] = av.w;
        *(float4*)&Bs[brow][bcol] = bv;
        __syncthreads();
        #pragma unroll
        for (int kk = 0; kk < BK; kk++) {
            float a[8], b[8];
            *(float4*)(a)     = *(const float4*)&As[kk][ty * 8];
            *(float4*)(a + 4) = *(const float4*)&As[kk][ty * 8 + 4];
            *(float4*)(b)     = *(const float4*)&Bs[kk][tx * 8];
            *(float4*)(b + 4) = *(const float4*)&Bs[kk][tx * 8 + 4];
            #pragma unroll
            for (int i = 0; i < 8; i++)
                #pragma unroll
                for (int j = 0; j < 8; j++)
                    acc[i][j] += a[i] * b[j];
        }
        __syncthreads();
    }

    float bb[8] = {0, 0, 0, 0, 0, 0, 0, 0};
    if (bias) {
        *(float4*)(bb)     = *(const float4*)(bias + col0 + tx * 8);
        *(float4*)(bb + 4) = *(const float4*)(bias + col0 + tx * 8 + 4);
    }
    #pragma unroll
    for (int i = 0; i < 8; i++) {
        float vals[8];
        #pragma unroll
        for (int j = 0; j < 8; j++) {
            float v = acc[i][j] + bb[j];
            if (act == 1) v = tanhf(v);
            else if (act == 2) v = fmaxf(v, 0.f);
            vals[j] = v;
        }
        float* crow = C + (size_t)(row0 + ty * 8 + i) * HIDD + col0 + tx * 8;
        *(float4*)(crow)     = *(float4*)(vals);
        *(float4*)(crow + 4) = *(float4*)(vals + 4);
    }
}

// ---------------- GCN aggregation: one CTA per graph ----------------
// out[d] = dis[d]*( sum_{s in in(d)} dis[s]*t[s]  +  dis[d]*t[d] ) + bias
__global__ __launch_bounds__(512) void k_agg(
    const float* __restrict__ t, const float* __restrict__ bias,
    float* __restrict__ out)
{
    extern __shared__ float4 s4[];          // 100 rows x 128 float4 (204800 B)
    __shared__ float sdis[NPG];
    int g = blockIdx.x, base = g * NPG;
    int tid = threadIdx.x;

    if (tid < NPG) sdis[tid] = g_dis[base + tid];
    __syncthreads();

    const float4* t4 = (const float4*)(t + (size_t)base * HIDD);
    for (int i = tid; i < NPG * 128; i += 512) {
        int row = i >> 7;
        float4 v = t4[i];
        float d = sdis[row];
        v.x *= d; v.y *= d; v.z *= d; v.w *= d;
        s4[i] = v;
    }
    __syncthreads();

    int rid = tid >> 7, cid = tid & 127;     // 4 dst rows in flight, 128 threads each
    float4 bv = ((const float4*)bias)[cid];
    float4* out4 = (float4*)(out + (size_t)base * HIDD);

    for (int r0 = 0; r0 < NPG; r0 += 4) {
        int row = r0 + rid;
        float4 acc = s4[row * 128 + cid];    // self loop term (already dis-scaled)
        int p0 = g_ptr[base + row], p1 = g_ptr[base + row + 1];
        for (int p = p0; p < p1; p++) {
            int sl = g_csrc[p] - base;
            float4 v = s4[sl * 128 + cid];
            acc.x += v.x; acc.y += v.y; acc.z += v.z; acc.w += v.w;
        }
        float d = sdis[row];
        acc.x = acc.x * d + bv.x;
        acc.y = acc.y * d + bv.y;
        acc.z = acc.z * d + bv.z;
        acc.w = acc.w * d + bv.w;
        out4[row * 128 + cid] = acc;
    }
}

// ---------------- assignment head: one warp per node ----------------
__global__ void k_assign(const float* __restrict__ t1,
                         const float* __restrict__ Wc2,
                         const float* __restrict__ bc2)
{
    int w = (blockIdx.x * blockDim.x + threadIdx.x) >> 5;
    int lane = threadIdx.x & 31;
    if (w >= NN) return;
    const float* row = t1 + (size_t)w * HIDD;
    float a0 = 0.f, a1 = 0.f;
    for (int k = lane; k < HIDD; k += 32) {
        float v = row[k];
        a0 += v * Wc2[k * 2];
        a1 += v * Wc2[k * 2 + 1];
    }
    #pragma unroll
    for (int o = 16; o; o >>= 1) {
        a0 += __shfl_down_sync(0xffffffffu, a0, o);
        a1 += __shfl_down_sync(0xffffffffu, a1, o);
    }
    if (lane == 0) {
        a0 += bc2[0]; a1 += bc2[1];
        float m = fmaxf(a0, a1);
        float e0 = expf(a0 - m), e1 = expf(a1 - m);
        float s = 1.f / (e0 + e1);
        g_assign[w * 2]     = e0 * s;
        g_assign[w * 2 + 1] = e1 * s;
    }
}

// ---------------- pos pooling: CTA per graph ----------------
__global__ __launch_bounds__(512) void k_pos(const float* __restrict__ h) {
    int g = blockIdx.x, c = threadIdx.x;
    int base = g * NPG;
    float acc = 0.f;
    for (int i = 0; i < NPG; i++)
        acc += g_assign[(base + i) * 2] * h[(size_t)(base + i) * HIDD + c];
    g_pos[g * HIDD + c] = acc;
}

// ---------------- new_adj accumulation ----------------
__global__ void k_adj(const int* __restrict__ src, const int* __restrict__ dst) {
    int e = blockIdx.x * blockDim.x + threadIdx.x;
    if (e >= NE) return;
    int s = src[e], d = dst[e];
    int g = s / NPG;
    float s0 = g_assign[s * 2], s1 = g_assign[s * 2 + 1];
    float d0 = g_assign[d * 2], d1 = g_assign[d * 2 + 1];
    float v00 = s0 * d0, v01 = s0 * d1, v10 = s1 * d0, v11 = s1 * d1;
    unsigned m = 0xffffffffu;
    int g0 = __shfl_sync(m, g, 0);
    bool uni = __all_sync(m, g == g0);
    if (uni) {
        #pragma unroll
        for (int o = 16; o; o >>= 1) {
            v00 += __shfl_down_sync(m, v00, o);
            v01 += __shfl_down_sync(m, v01, o);
            v10 += __shfl_down_sync(m, v10, o);
            v11 += __shfl_down_sync(m, v11, o);
        }
        if ((threadIdx.x & 31) == 0) {
            atomicAdd(&g_adj[g * 4 + 0], v00);
            atomicAdd(&g_adj[g * 4 + 1], v01);
            atomicAdd(&g_adj[g * 4 + 2], v10);
            atomicAdd(&g_adj[g * 4 + 3], v11);
        }
    } else {
        atomicAdd(&g_adj[g * 4 + 0], v00);
        atomicAdd(&g_adj[g * 4 + 1], v01);
        atomicAdd(&g_adj[g * 4 + 2], v10);
        atomicAdd(&g_adj[g * 4 + 3], v11);
    }
}

__global__ __launch_bounds__(512) void k_penalty(float* __restrict__ out) {
    __shared__ float red[512];
    int g = threadIdx.x;
    float a00 = g_adj[g * 4], a01 = g_adj[g * 4 + 1];
    float a10 = g_adj[g * 4 + 2], a11 = g_adj[g * 4 + 3];
    float l0 = fmaxf(fabsf(a00) + fabsf(a01), EPSV);
    float l1 = fmaxf(fabsf(a10) + fabsf(a11), EPSV);
    float d0 = a00 / l0 - 1.f, d1 = a11 / l1 - 1.f;
    red[g] = d0 * d0 + d1 * d1;
    __syncthreads();
    for (int o = 256; o; o >>= 1) {
        if (g < o) red[g] += red[g + o];
        __syncthreads();
    }
    if (g == 0) out[OFF_PEN] = red[0] / (2.f * NG);
}

// ---------------- gemb (global mean) ----------------
__global__ __launch_bounds__(512) void k_colsum(const float* __restrict__ h) {
    int c = threadIdx.x;
    int n0 = blockIdx.x * 256;
    float acc = 0.f;
    for (int i = 0; i < 256; i++)
        acc += h[(size_t)(n0 + i) * HIDD + c];
    atomicAdd(&g_colsum[c], acc);
}

__global__ __launch_bounds__(512) void k_gemb() {
    __shared__ float red[512];
    __shared__ float s_s;
    int c = threadIdx.x;
    float m = g_colsum[c] * (1.0f / NN);
    red[c] = m * m;
    __syncthreads();
    for (int o = 256; o; o >>= 1) {
        if (c < o) red[c] += red[c + o];
        __syncthreads();
    }
    if (c == 0) {
        float p = sqrtf(red[0] / HIDD);
        s_s = (p > 1.f) ? 1.f / p : 1.f;
    }
    __syncthreads();
    g_m[c] = m * s_s;
}

__global__ __launch_bounds__(512) void k_bcast(float* __restrict__ out) {
    out[OFF_GEMB + blockIdx.x * HIDD + threadIdx.x] = g_m[threadIdx.x];
}

// ---------------- pos normalization ----------------
__global__ __launch_bounds__(512) void k_sumsq() {
    __shared__ float red[512];
    int i = blockIdx.x * 512 + threadIdx.x;
    float v = g_pos[i];
    red[threadIdx.x] = v * v;
    __syncthreads();
    for (int o = 256; o; o >>= 1) {
        if (threadIdx.x < o) red[threadIdx.x] += red[threadIdx.x + o];
        __syncthreads();
    }
    if (threadIdx.x == 0) atomicAdd(&g_scal[0], red[0]);
}

__global__ __launch_bounds__(512) void k_scale_pos(float* __restrict__ out) {
    int i = blockIdx.x * 512 + threadIdx.x;
    float p = sqrtf(g_scal[0] / (float)(NG * HIDD));
    float s = (p > 1.f) ? 1.f / p : 1.f;
    float v = g_pos[i] * s;
    g_pos[i] = v;
    out[OFF_POS + i] = v;
}

// ---------------- classifier head: one warp per graph ----------------
__global__ void k_head(const float* __restrict__ t2,
                       const float* __restrict__ Wl2,
                       const float* __restrict__ bl2,
                       float* __restrict__ out)
{
    int w = (blockIdx.x * blockDim.x + threadIdx.x) >> 5;
    int lane = threadIdx.x & 31;
    if (w >= NG) return;
    const float* row = t2 + (size_t)w * HIDD;
    float acc[NCLS] = {0, 0, 0, 0, 0, 0};
    for (int k = lane; k < HIDD; k += 32) {
        float v = row[k];
        #pragma unroll
        for (int j = 0; j < NCLS; j++)
            acc[j] += v * Wl2[k * NCLS + j];
    }
    #pragma unroll
    for (int j = 0; j < NCLS; j++)
        #pragma unroll
        for (int o = 16; o; o >>= 1)
            acc[j] += __shfl_down_sync(0xffffffffu, acc[j], o);
    if (lane == 0) {
        float o_[NCLS];
        float m = -1e30f;
        #pragma unroll
        for (int j = 0; j < NCLS; j++) { o_[j] = acc[j] + bl2[j]; m = fmaxf(m, o_[j]); }
        float s = 0.f;
        #pragma unroll
        for (int j = 0; j < NCLS; j++) s += expf(o_[j] - m);
        float lse = logf(s) + m;
        #pragma unroll
        for (int j = 0; j < NCLS; j++)
            out[OFF_LOGP + w * NCLS + j] = o_[j] - lse;
    }
}

// ---------------- launch ----------------
extern "C" void kernel_launch(void* const* d_in, const int* in_sizes, int n_in,
                              void* d_out, int out_size)
{
    const float* x   = (const float*)d_in[0];
    const int*   ei  = (const int*)d_in[1];
    // d_in[2] = batch (structure known), d_in[3] = snr (0 -> no noise)
    const float* W1  = (const float*)d_in[4];
    const float* b1  = (const float*)d_in[5];
    const float* W2  = (const float*)d_in[6];
    const float* b2  = (const float*)d_in[7];
    const float* W3  = (const float*)d_in[8];
    const float* b3  = (const float*)d_in[9];
    const float* Wc1 = (const float*)d_in[10];
    const float* bc1 = (const float*)d_in[11];
    const float* Wc2 = (const float*)d_in[12];
    const float* bc2 = (const float*)d_in[13];
    const float* Wl1 = (const float*)d_in[14];
    const float* bl1 = (const float*)d_in[15];
    const float* Wl2 = (const float*)d_in[16];
    const float* bl2 = (const float*)d_in[17];
    float* out = (float*)d_out;

    const int* src = ei;
    const int* dst = ei + NE;

    void *pA, *pB, *pPos, *pCnt, *pAdj, *pCol, *pScal;
    cudaGetSymbolAddress(&pA, g_bufA);
    cudaGetSymbolAddress(&pB, g_bufB);
    cudaGetSymbolAddress(&pPos, g_pos);
    cudaGetSymbolAddress(&pCnt, g_cnt);
    cudaGetSymbolAddress(&pAdj, g_adj);
    cudaGetSymbolAddress(&pCol, g_colsum);
    cudaGetSymbolAddress(&pScal, g_scal);
    float* bufA = (float*)pA;
    float* bufB = (float*)pB;
    float* pos  = (float*)pPos;

    cudaFuncSetAttribute(k_agg, cudaFuncAttributeMaxDynamicSharedMemorySize,
                         NPG * HIDD * (int)sizeof(float));

    cudaMemsetAsync(pCnt, 0, NN * sizeof(int));
    cudaMemsetAsync(pAdj, 0, NG * 4 * sizeof(float));
    cudaMemsetAsync(pCol, 0, HIDD * sizeof(float));
    cudaMemsetAsync(pScal, 0, 4 * sizeof(float));

    // CSR build + degree norm
    k_count<<<NE / 256, 256>>>(dst);
    k_scan<<<2, 256>>>();
    k_fill<<<NE / 256, 256>>>(src, dst);

    const int SMEM_AGG = NPG * HIDD * (int)sizeof(float);
    dim3 gemm_grid_big(HIDD / BN, NN / BM);
    dim3 gemm_grid_small(HIDD / BN, NG / BM);

    // 3 GCN layers
    gemm512<<<gemm_grid_big, 256>>>(x, W1, nullptr, bufB, NN, FIN, 0);
    k_agg<<<NG, 512, SMEM_AGG>>>(bufB, b1, bufA);
    gemm512<<<gemm_grid_big, 256>>>(bufA, W2, nullptr, bufB, NN, HIDD, 0);
    k_agg<<<NG, 512, SMEM_AGG>>>(bufB, b2, bufA);
    gemm512<<<gemm_grid_big, 256>>>(bufA, W3, nullptr, bufB, NN, HIDD, 0);
    k_agg<<<NG, 512, SMEM_AGG>>>(bufB, b3, bufA);   // bufA = h3

    // assignment = softmax(tanh(h3@Wc1+bc1)@Wc2+bc2)
    gemm512<<<gemm_grid_big, 256>>>(bufA, Wc1, bc1, bufB, NN, HIDD, 1);
    k_assign<<<NN / 8, 256>>>(bufB, Wc2, bc2);

    // pooled pos, adjacency penalty, gemb
    k_pos<<<NG, 512>>>(bufA);
    k_adj<<<NE / 256, 256>>>(src, dst);
    k_penalty<<<1, 512>>>(out);
    k_colsum<<<NN / 256, 512>>>(bufA);
    k_gemb<<<1, 512>>>();
    k_bcast<<<NG, 512>>>(out);

    // pos power-normalization
    k_sumsq<<<NG * HIDD / 512, 512>>>();
    k_scale_pos<<<NG * HIDD / 512, 512>>>(out);

    // classifier
    gemm512<<<gemm_grid_small, 256>>>(pos, Wl1, bl1, bufB, NG, HIDD, 2);
    k_head<<<NG / 8, 256>>>(bufB, Wl2, bl2, out);
}

// round 3
// speedup vs baseline: 1.0373x; 1.0373x over previous
#include <cuda_runtime.h>
#include <math.h>

// ---------------- problem constants ----------------
#define NN   51200      // nodes
#define NPG  100        // nodes per graph
#define NG   512        // graphs
#define EPG  1600       // edges per graph
#define NE   819200     // edges
#define FIN  128
#define HIDD 512
#define NCLS 6
#define EPSV 1e-5f

// output layout: (logp[NG*6], pos[NG*512], gemb[NG*512], penalty[1])
#define OFF_LOGP 0
#define OFF_POS  (NG * NCLS)
#define OFF_GEMB (OFF_POS + NG * HIDD)
#define OFF_PEN  (OFF_GEMB + NG * HIDD)

typedef unsigned long long u64t;

// packed fp32x2 FMA (SASS FFMA2) — only reachable via PTX
__device__ __forceinline__ u64t ffma2(u64t a, u64t b, u64t c) {
    u64t d;
    asm("fma.rn.f32x2 %0, %1, %2, %3;" : "=l"(d) : "l"(a), "l"(b), "l"(c));
    return d;
}
__device__ __forceinline__ u64t pack2(float lo, float hi) {
    u64t d;
    asm("mov.b64 %0, {%1, %2};" : "=l"(d) : "f"(lo), "f"(hi));
    return d;
}

// ---------------- device scratch ----------------
__device__ float g_bufA[(size_t)NN * HIDD];
__device__ float g_bufB[(size_t)NN * HIDD];
__device__ float g_dis[NN];
__device__ int   g_cnt[NN];
__device__ int   g_ptr[NN + 1];
__device__ int   g_cur[NN];
__device__ int   g_csrc[NE];
__device__ float g_assign[NN * 2];
__device__ float g_pos[NG * HIDD];
__device__ float g_adj[NG * 4];
__device__ float g_colsum[HIDD];
__device__ float g_m[HIDD];
__device__ float g_scal[4];

// ---------------- CSR build ----------------
__global__ void k_count(const int* __restrict__ dst) {
    int e = blockIdx.x * blockDim.x + threadIdx.x;
    if (e < NE) atomicAdd(&g_cnt[dst[e]], 1);
}

// one thread per graph: prefix-scan the 100 counts, compute dis
__global__ void k_scan() {
    int g = blockIdx.x * blockDim.x + threadIdx.x;
    if (g >= NG) return;
    int base = g * NPG;
    int run = g * EPG;
    for (int i = 0; i < NPG; i++) {
        int c = g_cnt[base + i];
        g_ptr[base + i] = run;
        g_cur[base + i] = run;
        g_dis[base + i] = rsqrtf((float)c + 1.0f);
        run += c;
    }
    if (g == NG - 1) g_ptr[NN] = run;
}

__global__ void k_fill(const int* __restrict__ src, const int* __restrict__ dst) {
    int e = blockIdx.x * blockDim.x + threadIdx.x;
    if (e < NE) {
        int d = dst[e];
        int p = atomicAdd(&g_cur[d], 1);
        g_csrc[p] = src[e];
    }
}

// ---------------- fp32 GEMM, N fixed = 512, packed FFMA2 mainloop ----------
// C[M,512] = act(A[M,K] @ B[K,512] + bias)
#define BM 128
#define BN 128
#define BK 8
__global__ __launch_bounds__(256, 2) void gemm512(
    const float* __restrict__ A, const float* __restrict__ B,
    const float* __restrict__ bias, float* __restrict__ C,
    int M, int K, int act)
{
    __shared__ float As[BK][BM + 4];   // padded to kill store conflicts
    __shared__ float Bs[BK][BN];

    int tid = threadIdx.x;
    int row0 = blockIdx.y * BM, col0 = blockIdx.x * BN;

    int arow = tid >> 1, ak4 = (tid & 1) * 4;      // A tile: 128 rows x 8 k
    int brow = tid >> 5, bcol = (tid & 31) * 4;    // B tile: 8 k x 128 cols
    int tx = tid & 15, ty = tid >> 4;

    // acc2[ip][j] packs output rows (2ip, 2ip+1) for column j
    u64t acc2[4][8];
    #pragma unroll
    for (int i = 0; i < 4; i++)
        #pragma unroll
        for (int j = 0; j < 8; j++) acc2[i][j] = 0ull;

    const float* Abase = A + (size_t)(row0 + arow) * K + ak4;
    const float* Bbase = B + (size_t)brow * HIDD + col0 + bcol;

    // prologue: stage first tiles in registers
    float4 av = *(const float4*)Abase;
    float4 bv = *(const float4*)Bbase;

    for (int k0 = 0; k0 < K; k0 += BK) {
        As[ak4 + 0][arow] = av.x;
        As[ak4 + 1][arow] = av.y;
        As[ak4 + 2][arow] = av.z;
        As[ak4 + 3][arow] = av.w;
        *(float4*)&Bs[brow][bcol] = bv;
        __syncthreads();

        // prefetch next tile while computing this one
        if (k0 + BK < K) {
            av = *(const float4*)(Abase + (k0 + BK));
            bv = *(const float4*)(Bbase + (size_t)(k0 + BK) * HIDD);
        }

        #pragma unroll
        for (int kk = 0; kk < BK; kk++) {
            float4 a01 = *(const float4*)&As[kk][ty * 8];
            float4 a23 = *(const float4*)&As[kk][ty * 8 + 4];
            float4 b01 = *(const float4*)&Bs[kk][tx * 8];
            float4 b23 = *(const float4*)&Bs[kk][tx * 8 + 4];

            // row pairs come straight out of the float4s
            u64t ap[4];
            ap[0] = ((const u64t*)&a01)[0];
            ap[1] = ((const u64t*)&a01)[1];
            ap[2] = ((const u64t*)&a23)[0];
            ap[3] = ((const u64t*)&a23)[1];

            // duplicated B operands (ALU pipe, hides under FMA pipe)
            u64t bb[8];
            bb[0] = pack2(b01.x, b01.x);
            bb[1] = pack2(b01.y, b01.y);
            bb[2] = pack2(b01.z, b01.z);
            bb[3] = pack2(b01.w, b01.w);
            bb[4] = pack2(b23.x, b23.x);
            bb[5] = pack2(b23.y, b23.y);
            bb[6] = pack2(b23.z, b23.z);
            bb[7] = pack2(b23.w, b23.w);

            #pragma unroll
            for (int j = 0; j < 8; j++)
                #pragma unroll
                for (int ip = 0; ip < 4; ip++)
                    acc2[ip][j] = ffma2(ap[ip], bb[j], acc2[ip][j]);
        }
        __syncthreads();
    }

    float bb_[8] = {0, 0, 0, 0, 0, 0, 0, 0};
    if (bias) {
        *(float4*)(bb_)     = *(const float4*)(bias + col0 + tx * 8);
        *(float4*)(bb_ + 4) = *(const float4*)(bias + col0 + tx * 8 + 4);
    }
    #pragma unroll
    for (int ip = 0; ip < 4; ip++) {
        float lo[8], hi[8];
        #pragma unroll
        for (int j = 0; j < 8; j++) {
            float2 u = *(float2*)&acc2[ip][j];
            float v0 = u.x + bb_[j];
            float v1 = u.y + bb_[j];
            if (act == 1)      { v0 = tanhf(v0);     v1 = tanhf(v1);     }
            else if (act == 2) { v0 = fmaxf(v0, 0.f); v1 = fmaxf(v1, 0.f); }
            lo[j] = v0; hi[j] = v1;
        }
        float* crow0 = C + (size_t)(row0 + ty * 8 + 2 * ip)     * HIDD + col0 + tx * 8;
        float* crow1 = C + (size_t)(row0 + ty * 8 + 2 * ip + 1) * HIDD + col0 + tx * 8;
        *(float4*)(crow0)     = *(float4*)(lo);
        *(float4*)(crow0 + 4) = *(float4*)(lo + 4);
        *(float4*)(crow1)     = *(float4*)(hi);
        *(float4*)(crow1 + 4) = *(float4*)(hi + 4);
    }
}

// ---------------- GCN aggregation: one CTA per graph ----------------
// out[d] = dis[d]*( sum_{s in in(d)} dis[s]*t[s]  +  dis[d]*t[d] ) + bias
__global__ __launch_bounds__(512) void k_agg(
    const float* __restrict__ t, const float* __restrict__ bias,
    float* __restrict__ out)
{
    extern __shared__ float4 s4[];          // 100 rows x 128 float4 (204800 B)
    __shared__ float sdis[NPG];
    int g = blockIdx.x, base = g * NPG;
    int tid = threadIdx.x;

    if (tid < NPG) sdis[tid] = g_dis[base + tid];
    __syncthreads();

    const float4* t4 = (const float4*)(t + (size_t)base * HIDD);
    for (int i = tid; i < NPG * 128; i += 512) {
        int row = i >> 7;
        float4 v = t4[i];
        float d = sdis[row];
        v.x *= d; v.y *= d; v.z *= d; v.w *= d;
        s4[i] = v;
    }
    __syncthreads();

    int rid = tid >> 7, cid = tid & 127;     // 4 dst rows in flight, 128 threads each
    float4 bv = ((const float4*)bias)[cid];
    float4* out4 = (float4*)(out + (size_t)base * HIDD);

    for (int r0 = 0; r0 < NPG; r0 += 4) {
        int row = r0 + rid;
        float4 acc = s4[row * 128 + cid];    // self loop term (already dis-scaled)
        int p0 = g_ptr[base + row], p1 = g_ptr[base + row + 1];
        for (int p = p0; p < p1; p++) {
            int sl = g_csrc[p] - base;
            float4 v = s4[sl * 128 + cid];
            acc.x += v.x; acc.y += v.y; acc.z += v.z; acc.w += v.w;
        }
        float d = sdis[row];
        acc.x = acc.x * d + bv.x;
        acc.y = acc.y * d + bv.y;
        acc.z = acc.z * d + bv.z;
        acc.w = acc.w * d + bv.w;
        out4[row * 128 + cid] = acc;
    }
}

// ---------------- assignment head: one warp per node ----------------
__global__ void k_assign(const float* __restrict__ t1,
                         const float* __restrict__ Wc2,
                         const float* __restrict__ bc2)
{
    int w = (blockIdx.x * blockDim.x + threadIdx.x) >> 5;
    int lane = threadIdx.x & 31;
    if (w >= NN) return;
    const float* row = t1 + (size_t)w * HIDD;
    float a0 = 0.f, a1 = 0.f;
    for (int k = lane; k < HIDD; k += 32) {
        float v = row[k];
        a0 += v * Wc2[k * 2];
        a1 += v * Wc2[k * 2 + 1];
    }
    #pragma unroll
    for (int o = 16; o; o >>= 1) {
        a0 += __shfl_down_sync(0xffffffffu, a0, o);
        a1 += __shfl_down_sync(0xffffffffu, a1, o);
    }
    if (lane == 0) {
        a0 += bc2[0]; a1 += bc2[1];
        float m = fmaxf(a0, a1);
        float e0 = expf(a0 - m), e1 = expf(a1 - m);
        float s = 1.f / (e0 + e1);
        g_assign[w * 2]     = e0 * s;
        g_assign[w * 2 + 1] = e1 * s;
    }
}

// ---------------- pos pooling: CTA per graph ----------------
__global__ __launch_bounds__(512) void k_pos(const float* __restrict__ h) {
    int g = blockIdx.x, c = threadIdx.x;
    int base = g * NPG;
    float acc = 0.f;
    for (int i = 0; i < NPG; i++)
        acc += g_assign[(base + i) * 2] * h[(size_t)(base + i) * HIDD + c];
    g_pos[g * HIDD + c] = acc;
}

// ---------------- new_adj accumulation ----------------
__global__ void k_adj(const int* __restrict__ src, const int* __restrict__ dst) {
    int e = blockIdx.x * blockDim.x + threadIdx.x;
    if (e >= NE) return;
    int s = src[e], d = dst[e];
    int g = s / NPG;
    float s0 = g_assign[s * 2], s1 = g_assign[s * 2 + 1];
    float d0 = g_assign[d * 2], d1 = g_assign[d * 2 + 1];
    float v00 = s0 * d0, v01 = s0 * d1, v10 = s1 * d0, v11 = s1 * d1;
    unsigned m = 0xffffffffu;
    int g0 = __shfl_sync(m, g, 0);
    bool uni = __all_sync(m, g == g0);
    if (uni) {
        #pragma unroll
        for (int o = 16; o; o >>= 1) {
            v00 += __shfl_down_sync(m, v00, o);
            v01 += __shfl_down_sync(m, v01, o);
            v10 += __shfl_down_sync(m, v10, o);
            v11 += __shfl_down_sync(m, v11, o);
        }
        if ((threadIdx.x & 31) == 0) {
            atomicAdd(&g_adj[g * 4 + 0], v00);
            atomicAdd(&g_adj[g * 4 + 1], v01);
            atomicAdd(&g_adj[g * 4 + 2], v10);
            atomicAdd(&g_adj[g * 4 + 3], v11);
        }
    } else {
        atomicAdd(&g_adj[g * 4 + 0], v00);
        atomicAdd(&g_adj[g * 4 + 1], v01);
        atomicAdd(&g_adj[g * 4 + 2], v10);
        atomicAdd(&g_adj[g * 4 + 3], v11);
    }
}

__global__ __launch_bounds__(512) void k_penalty(float* __restrict__ out) {
    __shared__ float red[512];
    int g = threadIdx.x;
    float a00 = g_adj[g * 4], a01 = g_adj[g * 4 + 1];
    float a10 = g_adj[g * 4 + 2], a11 = g_adj[g * 4 + 3];
    float l0 = fmaxf(fabsf(a00) + fabsf(a01), EPSV);
    float l1 = fmaxf(fabsf(a10) + fabsf(a11), EPSV);
    float d0 = a00 / l0 - 1.f, d1 = a11 / l1 - 1.f;
    red[g] = d0 * d0 + d1 * d1;
    __syncthreads();
    for (int o = 256; o; o >>= 1) {
        if (g < o) red[g] += red[g + o];
        __syncthreads();
    }
    if (g == 0) out[OFF_PEN] = red[0] / (2.f * NG);
}

// ---------------- gemb (global mean) ----------------
__global__ __launch_bounds__(512) void k_colsum(const float* __restrict__ h) {
    int c = threadIdx.x;
    int n0 = blockIdx.x * 256;
    float acc = 0.f;
    for (int i = 0; i < 256; i++)
        acc += h[(size_t)(n0 + i) * HIDD + c];
    atomicAdd(&g_colsum[c], acc);
}

__global__ __launch_bounds__(512) void k_gemb() {
    __shared__ float red[512];
    __shared__ float s_s;
    int c = threadIdx.x;
    float m = g_colsum[c] * (1.0f / NN);
    red[c] = m * m;
    __syncthreads();
    for (int o = 256; o; o >>= 1) {
        if (c < o) red[c] += red[c + o];
        __syncthreads();
    }
    if (c == 0) {
        float p = sqrtf(red[0] / HIDD);
        s_s = (p > 1.f) ? 1.f / p : 1.f;
    }
    __syncthreads();
    g_m[c] = m * s_s;
}

__global__ __launch_bounds__(512) void k_bcast(float* __restrict__ out) {
    out[OFF_GEMB + blockIdx.x * HIDD + threadIdx.x] = g_m[threadIdx.x];
}

// ---------------- pos normalization ----------------
__global__ __launch_bounds__(512) void k_sumsq() {
    __shared__ float red[512];
    int i = blockIdx.x * 512 + threadIdx.x;
    float v = g_pos[i];
    red[threadIdx.x] = v * v;
    __syncthreads();
    for (int o = 256; o; o >>= 1) {
        if (threadIdx.x < o) red[threadIdx.x] += red[threadIdx.x + o];
        __syncthreads();
    }
    if (threadIdx.x == 0) atomicAdd(&g_scal[0], red[0]);
}

__global__ __launch_bounds__(512) void k_scale_pos(float* __restrict__ out) {
    int i = blockIdx.x * 512 + threadIdx.x;
    float p = sqrtf(g_scal[0] / (float)(NG * HIDD));
    float s = (p > 1.f) ? 1.f / p : 1.f;
    float v = g_pos[i] * s;
    g_pos[i] = v;
    out[OFF_POS + i] = v;
}

// ---------------- classifier head: one warp per graph ----------------
__global__ void k_head(const float* __restrict__ t2,
                       const float* __restrict__ Wl2,
                       const float* __restrict__ bl2,
                       float* __restrict__ out)
{
    int w = (blockIdx.x * blockDim.x + threadIdx.x) >> 5;
    int lane = threadIdx.x & 31;
    if (w >= NG) return;
    const float* row = t2 + (size_t)w * HIDD;
    float acc[NCLS] = {0, 0, 0, 0, 0, 0};
    for (int k = lane; k < HIDD; k += 32) {
        float v = row[k];
        #pragma unroll
        for (int j = 0; j < NCLS; j++)
            acc[j] += v * Wl2[k * NCLS + j];
    }
    #pragma unroll
    for (int j = 0; j < NCLS; j++)
        #pragma unroll
        for (int o = 16; o; o >>= 1)
            acc[j] += __shfl_down_sync(0xffffffffu, acc[j], o);
    if (lane == 0) {
        float o_[NCLS];
        float m = -1e30f;
        #pragma unroll
        for (int j = 0; j < NCLS; j++) { o_[j] = acc[j] + bl2[j]; m = fmaxf(m, o_[j]); }
        float s = 0.f;
        #pragma unroll
        for (int j = 0; j < NCLS; j++) s += expf(o_[j] - m);
        float lse = logf(s) + m;
        #pragma unroll
        for (int j = 0; j < NCLS; j++)
            out[OFF_LOGP + w * NCLS + j] = o_[j] - lse;
    }
}

// ---------------- launch ----------------
extern "C" void kernel_launch(void* const* d_in, const int* in_sizes, int n_in,
                              void* d_out, int out_size)
{
    const float* x   = (const float*)d_in[0];
    const int*   ei  = (const int*)d_in[1];
    // d_in[2] = batch (structure known), d_in[3] = snr (0 -> no noise)
    const float* W1  = (const float*)d_in[4];
    const float* b1  = (const float*)d_in[5];
    const float* W2  = (const float*)d_in[6];
    const float* b2  = (const float*)d_in[7];
    const float* W3  = (const float*)d_in[8];
    const float* b3  = (const float*)d_in[9];
    const float* Wc1 = (const float*)d_in[10];
    const float* bc1 = (const float*)d_in[11];
    const float* Wc2 = (const float*)d_in[12];
    const float* bc2 = (const float*)d_in[13];
    const float* Wl1 = (const float*)d_in[14];
    const float* bl1 = (const float*)d_in[15];
    const float* Wl2 = (const float*)d_in[16];
    const float* bl2 = (const float*)d_in[17];
    float* out = (float*)d_out;

    const int* src = ei;
    const int* dst = ei + NE;

    void *pA, *pB, *pPos, *pCnt, *pAdj, *pCol, *pScal;
    cudaGetSymbolAddress(&pA, g_bufA);
    cudaGetSymbolAddress(&pB, g_bufB);
    cudaGetSymbolAddress(&pPos, g_pos);
    cudaGetSymbolAddress(&pCnt, g_cnt);
    cudaGetSymbolAddress(&pAdj, g_adj);
    cudaGetSymbolAddress(&pCol, g_colsum);
    cudaGetSymbolAddress(&pScal, g_scal);
    float* bufA = (float*)pA;
    float* bufB = (float*)pB;
    float* pos  = (float*)pPos;

    cudaFuncSetAttribute(k_agg, cudaFuncAttributeMaxDynamicSharedMemorySize,
                         NPG * HIDD * (int)sizeof(float));

    cudaMemsetAsync(pCnt, 0, NN * sizeof(int));
    cudaMemsetAsync(pAdj, 0, NG * 4 * sizeof(float));
    cudaMemsetAsync(pCol, 0, HIDD * sizeof(float));
    cudaMemsetAsync(pScal, 0, 4 * sizeof(float));

    // CSR build + degree norm
    k_count<<<NE / 256, 256>>>(dst);
    k_scan<<<2, 256>>>();
    k_fill<<<NE / 256, 256>>>(src, dst);

    const int SMEM_AGG = NPG * HIDD * (int)sizeof(float);
    dim3 gemm_grid_big(HIDD / BN, NN / BM);
    dim3 gemm_grid_small(HIDD / BN, NG / BM);

    // 3 GCN layers
    gemm512<<<gemm_grid_big, 256>>>(x, W1, nullptr, bufB, NN, FIN, 0);
    k_agg<<<NG, 512, SMEM_AGG>>>(bufB, b1, bufA);
    gemm512<<<gemm_grid_big, 256>>>(bufA, W2, nullptr, bufB, NN, HIDD, 0);
    k_agg<<<NG, 512, SMEM_AGG>>>(bufB, b2, bufA);
    gemm512<<<gemm_grid_big, 256>>>(bufA, W3, nullptr, bufB, NN, HIDD, 0);
    k_agg<<<NG, 512, SMEM_AGG>>>(bufB, b3, bufA);   // bufA = h3

    // assignment = softmax(tanh(h3@Wc1+bc1)@Wc2+bc2)
    gemm512<<<gemm_grid_big, 256>>>(bufA, Wc1, bc1, bufB, NN, HIDD, 1);
    k_assign<<<NN / 8, 256>>>(bufB, Wc2, bc2);

    // pooled pos, adjacency penalty, gemb
    k_pos<<<NG, 512>>>(bufA);
    k_adj<<<NE / 256, 256>>>(src, dst);
    k_penalty<<<1, 512>>>(out);
    k_colsum<<<NN / 256, 512>>>(bufA);
    k_gemb<<<1, 512>>>();
    k_bcast<<<NG, 512>>>(out);

    // pos power-normalization
    k_sumsq<<<NG * HIDD / 512, 512>>>();
    k_scale_pos<<<NG * HIDD / 512, 512>>>(out);

    // classifier
    gemm512<<<gemm_grid_small, 256>>>(pos, Wl1, bl1, bufB, NG, HIDD, 2);
    k_head<<<NG / 8, 256>>>(bufB, Wl2, bl2, out);
}

// round 6
// speedup vs baseline: 1.7550x; 1.6919x over previous
#include <cuda_runtime.h>
#include <cuda_bf16.h>
#include <math.h>
#include <stdint.h>

// ---------------- problem constants ----------------
#define NN   51200      // nodes
#define NPG  100        // nodes per graph
#define NG   512        // graphs
#define EPG  1600       // edges per graph
#define NE   819200     // edges
#define FIN  128
#define HIDD 512
#define NCLS 6
#define EPSV 1e-5f

// output layout: (logp[NG*6], pos[NG*512], gemb[NG*512], penalty[1])
#define OFF_LOGP 0
#define OFF_POS  (NG * NCLS)
#define OFF_GEMB (OFF_POS + NG * HIDD)
#define OFF_PEN  (OFF_GEMB + NG * HIDD)

// ---------------- device scratch ----------------
__device__ float g_bufA[(size_t)NN * HIDD];
__device__ float g_bufB[(size_t)NN * HIDD];
__device__ float g_dis[NN];
__device__ int   g_cnt[NN];
__device__ int   g_ptr[NN + 1];
__device__ int   g_cur[NN];
__device__ int   g_csrc[NE];
__device__ float g_assign[NN * 2];
__device__ float g_pos[NG * HIDD];
__device__ float g_adj[NG * 4];
__device__ float g_colsum[HIDD];
__device__ float g_m[HIDD];
__device__ float g_scal[4];

// bf16 hi/lo split buffers
__device__ __nv_bfloat16 g_ah[(size_t)NN * HIDD];   // activation hi
__device__ __nv_bfloat16 g_al[(size_t)NN * HIDD];   // activation lo
__device__ __nv_bfloat16 g_posh[NG * HIDD], g_posl[NG * HIDD];
__device__ __nv_bfloat16 g_w1h[HIDD * FIN],  g_w1l[HIDD * FIN];     // Wt: [N=512, K]
__device__ __nv_bfloat16 g_w2h[HIDD * HIDD], g_w2l[HIDD * HIDD];
__device__ __nv_bfloat16 g_w3h[HIDD * HIDD], g_w3l[HIDD * HIDD];
__device__ __nv_bfloat16 g_wc1h[HIDD * HIDD], g_wc1l[HIDD * HIDD];
__device__ __nv_bfloat16 g_wl1h[HIDD * HIDD], g_wl1l[HIDD * HIDD];

// ---------------- CSR build ----------------
__global__ void k_count(const int* __restrict__ dst) {
    int e = blockIdx.x * blockDim.x + threadIdx.x;
    if (e < NE) atomicAdd(&g_cnt[dst[e]], 1);
}

__global__ void k_scan() {
    int g = blockIdx.x * blockDim.x + threadIdx.x;
    if (g >= NG) return;
    int base = g * NPG;
    int run = g * EPG;
    for (int i = 0; i < NPG; i++) {
        int c = g_cnt[base + i];
        g_ptr[base + i] = run;
        g_cur[base + i] = run;
        g_dis[base + i] = rsqrtf((float)c + 1.0f);
        run += c;
    }
    if (g == NG - 1) g_ptr[NN] = run;
}

__global__ void k_fill(const int* __restrict__ src, const int* __restrict__ dst) {
    int e = blockIdx.x * blockDim.x + threadIdx.x;
    if (e < NE) {
        int d = dst[e];
        int p = atomicAdd(&g_cur[d], 1);
        g_csrc[p] = src[e];
    }
}

// ---------------- bf16 hi/lo conversions ----------------
__device__ __forceinline__ void split2(float v, __nv_bfloat16& h, __nv_bfloat16& l) {
    h = __float2bfloat16(v);
    l = __float2bfloat16(v - __bfloat162float(h));
}

__global__ void k_cvt_x(const float* __restrict__ x) {
    int i = blockIdx.x * blockDim.x + threadIdx.x;
    if (i < NN * FIN) {
        __nv_bfloat16 h, l;
        split2(x[i], h, l);
        g_ah[i] = h; g_al[i] = l;
    }
}

// W [K x 512] fp32 -> Wt hi/lo [512 x K] bf16
__global__ void k_cvt_w(const float* __restrict__ W,
                        __nv_bfloat16* __restrict__ oh,
                        __nv_bfloat16* __restrict__ ol, int K) {
    int i = blockIdx.x * blockDim.x + threadIdx.x;
    if (i < HIDD * K) {
        int n = i / K, k = i - n * K;
        __nv_bfloat16 h, l;
        split2(W[(size_t)k * HIDD + n], h, l);
        oh[i] = h; ol[i] = l;
    }
}

// ---------------- HMMA (mma.sync) helper ----------------
__device__ __forceinline__ void mma16816(float* c, const uint32_t* a,
                                         uint32_t b0, uint32_t b1) {
    asm volatile(
        "mma.sync.aligned.m16n8k16.row.col.f32.bf16.bf16.f32 "
        "{%0,%1,%2,%3}, {%4,%5,%6,%7}, {%8,%9}, {%0,%1,%2,%3};"
        : "+f"(c[0]), "+f"(c[1]), "+f"(c[2]), "+f"(c[3])
        : "r"(a[0]), "r"(a[1]), "r"(a[2]), "r"(a[3]), "r"(b0), "r"(b1));
}

// ---------------- tensor-core GEMM via mma.sync ------------------------------
// C[M,512] = act(A @ W + bias); A as bf16 hi/lo row-major [M,K] (lda=K),
// W as transposed bf16 hi/lo [512, K]. K multiple of 32.
// CTA tile 128x128, 8 warps in 4(M) x 2(N), warp tile 32x64.
// hi/lo split: C += Ah*Bh + Ah*Bl + Al*Bh (AlBl dropped, ~2^-16 rel).
#define SK 40   // padded smem K-stride (bf16): banks g*20+q all distinct

__global__ __launch_bounds__(256) void tgemm(
    const __nv_bfloat16* __restrict__ Ah, const __nv_bfloat16* __restrict__ Al, int lda,
    const __nv_bfloat16* __restrict__ Bh, const __nv_bfloat16* __restrict__ Bl,
    const float* __restrict__ bias, float* __restrict__ C, int K, int act)
{
    __shared__ __nv_bfloat16 sA[2][128][SK];   // [h/l][row][k]
    __shared__ __nv_bfloat16 sB[2][128][SK];   // [h/l][ncol][k]

    int tid = threadIdx.x;
    int lane = tid & 31, wid = tid >> 5;
    int wm = wid & 3, wn = wid >> 2;           // 4 x 2 warp grid
    int g = lane >> 2, q = lane & 3;
    int row0 = blockIdx.x * 128, col0 = blockIdx.y * 128;

    float acc[2][8][4];
    #pragma unroll
    for (int m = 0; m < 2; m++)
        #pragma unroll
        for (int j = 0; j < 8; j++)
            #pragma unroll
            for (int t = 0; t < 4; t++) acc[m][j][t] = 0.f;

    // global load mapping: per slab 512 uint4 (128 rows x 4 x 8bf16), 2/thread
    int r_ld[2], c_ld[2];
    #pragma unroll
    for (int it = 0; it < 2; it++) {
        int u = tid + it * 256;
        r_ld[it] = u >> 2;
        c_ld[it] = (u & 3) * 8;
    }

    uint4 va[2][2], vb[2][2];   // [slab][it]
    #pragma unroll
    for (int it = 0; it < 2; it++) {
        va[0][it] = *(const uint4*)(Ah + (size_t)(row0 + r_ld[it]) * lda + c_ld[it]);
        va[1][it] = *(const uint4*)(Al + (size_t)(row0 + r_ld[it]) * lda + c_ld[it]);
        vb[0][it] = *(const uint4*)(Bh + (size_t)(col0 + r_ld[it]) * K + c_ld[it]);
        vb[1][it] = *(const uint4*)(Bl + (size_t)(col0 + r_ld[it]) * K + c_ld[it]);
    }

    for (int k0 = 0; k0 < K; k0 += 32) {
        __syncthreads();          // previous compute done before overwrite
        #pragma unroll
        for (int it = 0; it < 2; it++) {
            *(uint4*)&sA[0][r_ld[it]][c_ld[it]] = va[0][it];
            *(uint4*)&sA[1][r_ld[it]][c_ld[it]] = va[1][it];
            *(uint4*)&sB[0][r_ld[it]][c_ld[it]] = vb[0][it];
            *(uint4*)&sB[1][r_ld[it]][c_ld[it]] = vb[1][it];
        }
        __syncthreads();

        if (k0 + 32 < K) {        // prefetch next tile during compute
            int kn = k0 + 32;
            #pragma unroll
            for (int it = 0; it < 2; it++) {
                va[0][it] = *(const uint4*)(Ah + (size_t)(row0 + r_ld[it]) * lda + kn + c_ld[it]);
                va[1][it] = *(const uint4*)(Al + (size_t)(row0 + r_ld[it]) * lda + kn + c_ld[it]);
                vb[0][it] = *(const uint4*)(Bh + (size_t)(col0 + r_ld[it]) * K + kn + c_ld[it]);
                vb[1][it] = *(const uint4*)(Bl + (size_t)(col0 + r_ld[it]) * K + kn + c_ld[it]);
            }
        }

        #pragma unroll
        for (int kk = 0; kk < 32; kk += 16) {
            #pragma unroll
            for (int p = 0; p < 3; p++) {          // (h,h), (h,l), (l,h)
                int sa = (p == 2) ? 1 : 0;
                int sb = (p == 1) ? 1 : 0;
                uint32_t a[2][4];
                #pragma unroll
                for (int m = 0; m < 2; m++) {
                    int r = wm * 32 + m * 16 + g;
                    a[m][0] = *(const uint32_t*)&sA[sa][r]    [kk + q * 2];
                    a[m][1] = *(const uint32_t*)&sA[sa][r + 8][kk + q * 2];
                    a[m][2] = *(const uint32_t*)&sA[sa][r]    [kk + q * 2 + 8];
                    a[m][3] = *(const uint32_t*)&sA[sa][r + 8][kk + q * 2 + 8];
                }
                #pragma unroll
                for (int j = 0; j < 8; j++) {
                    int n = wn * 64 + j * 8 + g;
                    uint32_t b0 = *(const uint32_t*)&sB[sb][n][kk + q * 2];
                    uint32_t b1 = *(const uint32_t*)&sB[sb][n][kk + q * 2 + 8];
                    mma16816(acc[0][j], a[0], b0, b1);
                    mma16816(acc[1][j], a[1], b0, b1);
                }
            }
        }
    }

    // epilogue: C rows r0=.. (c0,c1), r0+8 (c2,c3); cols j*8 + q*2
    #pragma unroll
    for (int m = 0; m < 2; m++) {
        int r = row0 + wm * 32 + m * 16 + g;
        #pragma unroll
        for (int j = 0; j < 8; j++) {
            int c = col0 + wn * 64 + j * 8 + q * 2;
            float b0 = 0.f, b1 = 0.f;
            if (bias) { b0 = bias[c]; b1 = bias[c + 1]; }
            float v0 = acc[m][j][0] + b0, v1 = acc[m][j][1] + b1;
            float v2 = acc[m][j][2] + b0, v3 = acc[m][j][3] + b1;
            if (act == 1) {
                v0 = tanhf(v0); v1 = tanhf(v1); v2 = tanhf(v2); v3 = tanhf(v3);
            } else if (act == 2) {
                v0 = fmaxf(v0, 0.f); v1 = fmaxf(v1, 0.f);
                v2 = fmaxf(v2, 0.f); v3 = fmaxf(v3, 0.f);
            }
            *(float2*)(C + (size_t)r * HIDD + c)       = make_float2(v0, v1);
            *(float2*)(C + (size_t)(r + 8) * HIDD + c) = make_float2(v2, v3);
        }
    }
}

// ---------------- GCN aggregation: one CTA per graph ----------------
// out[d] = dis[d]*( sum_{s in in(d)} dis[s]*t[s] + dis[d]*t[d] ) + bias
// also emits bf16 hi/lo of the output for the next tensor GEMM
__global__ __launch_bounds__(512) void k_agg(
    const float* __restrict__ t, const float* __restrict__ bias,
    float* __restrict__ out,
    __nv_bfloat16* __restrict__ outH, __nv_bfloat16* __restrict__ outL)
{
    extern __shared__ float4 s4[];          // 100 rows x 128 float4
    __shared__ float sdis[NPG];
    int g = blockIdx.x, base = g * NPG;
    int tid = threadIdx.x;

    if (tid < NPG) sdis[tid] = g_dis[base + tid];
    __syncthreads();

    const float4* t4 = (const float4*)(t + (size_t)base * HIDD);
    for (int i = tid; i < NPG * 128; i += 512) {
        int row = i >> 7;
        float4 v = t4[i];
        float d = sdis[row];
        v.x *= d; v.y *= d; v.z *= d; v.w *= d;
        s4[i] = v;
    }
    __syncthreads();

    int rid = tid >> 7, cid = tid & 127;
    float4 bv = ((const float4*)bias)[cid];
    float4* out4 = (float4*)(out + (size_t)base * HIDD);

    for (int r0 = 0; r0 < NPG; r0 += 4) {
        int row = r0 + rid;
        float4 acc = s4[row * 128 + cid];
        int p0 = g_ptr[base + row], p1 = g_ptr[base + row + 1];
        for (int p = p0; p < p1; p++) {
            int sl = g_csrc[p] - base;
            float4 v = s4[sl * 128 + cid];
            acc.x += v.x; acc.y += v.y; acc.z += v.z; acc.w += v.w;
        }
        float d = sdis[row];
        acc.x = acc.x * d + bv.x;
        acc.y = acc.y * d + bv.y;
        acc.z = acc.z * d + bv.z;
        acc.w = acc.w * d + bv.w;
        out4[row * 128 + cid] = acc;

        // bf16 hi/lo split of the same values
        size_t eb = (size_t)(base + row) * HIDD + cid * 4;
        __nv_bfloat16 hx, lx, hy, ly, hz, lz, hw, lw;
        split2(acc.x, hx, lx); split2(acc.y, hy, ly);
        split2(acc.z, hz, lz); split2(acc.w, hw, lw);
        *(__nv_bfloat162*)(outH + eb)     = __nv_bfloat162(hx, hy);
        *(__nv_bfloat162*)(outH + eb + 2) = __nv_bfloat162(hz, hw);
        *(__nv_bfloat162*)(outL + eb)     = __nv_bfloat162(lx, ly);
        *(__nv_bfloat162*)(outL + eb + 2) = __nv_bfloat162(lz, lw);
    }
}

// ---------------- assignment head: one warp per node ----------------
__global__ void k_assign(const float* __restrict__ t1,
                         const float* __restrict__ Wc2,
                         const float* __restrict__ bc2)
{
    int w = (blockIdx.x * blockDim.x + threadIdx.x) >> 5;
    int lane = threadIdx.x & 31;
    if (w >= NN) return;
    const float* row = t1 + (size_t)w * HIDD;
    float a0 = 0.f, a1 = 0.f;
    for (int k = lane; k < HIDD; k += 32) {
        float v = row[k];
        a0 += v * Wc2[k * 2];
        a1 += v * Wc2[k * 2 + 1];
    }
    #pragma unroll
    for (int o = 16; o; o >>= 1) {
        a0 += __shfl_down_sync(0xffffffffu, a0, o);
        a1 += __shfl_down_sync(0xffffffffu, a1, o);
    }
    if (lane == 0) {
        a0 += bc2[0]; a1 += bc2[1];
        float m = fmaxf(a0, a1);
        float e0 = expf(a0 - m), e1 = expf(a1 - m);
        float s = 1.f / (e0 + e1);
        g_assign[w * 2]     = e0 * s;
        g_assign[w * 2 + 1] = e1 * s;
    }
}

// ---------------- pos pooling: CTA per graph ----------------
__global__ __launch_bounds__(512) void k_pos(const float* __restrict__ h) {
    int g = blockIdx.x, c = threadIdx.x;
    int base = g * NPG;
    float acc = 0.f;
    for (int i = 0; i < NPG; i++)
        acc += g_assign[(base + i) * 2] * h[(size_t)(base + i) * HIDD + c];
    g_pos[g * HIDD + c] = acc;
}

// ---------------- new_adj accumulation ----------------
__global__ void k_adj(const int* __restrict__ src, const int* __restrict__ dst) {
    int e = blockIdx.x * blockDim.x + threadIdx.x;
    if (e >= NE) return;
    int s = src[e], d = dst[e];
    int g = s / NPG;
    float s0 = g_assign[s * 2], s1 = g_assign[s * 2 + 1];
    float d0 = g_assign[d * 2], d1 = g_assign[d * 2 + 1];
    float v00 = s0 * d0, v01 = s0 * d1, v10 = s1 * d0, v11 = s1 * d1;
    unsigned m = 0xffffffffu;
    int g0 = __shfl_sync(m, g, 0);
    bool uni = __all_sync(m, g == g0);
    if (uni) {
        #pragma unroll
        for (int o = 16; o; o >>= 1) {
            v00 += __shfl_down_sync(m, v00, o);
            v01 += __shfl_down_sync(m, v01, o);
            v10 += __shfl_down_sync(m, v10, o);
            v11 += __shfl_down_sync(m, v11, o);
        }
        if ((threadIdx.x & 31) == 0) {
            atomicAdd(&g_adj[g * 4 + 0], v00);
            atomicAdd(&g_adj[g * 4 + 1], v01);
            atomicAdd(&g_adj[g * 4 + 2], v10);
            atomicAdd(&g_adj[g * 4 + 3], v11);
        }
    } else {
        atomicAdd(&g_adj[g * 4 + 0], v00);
        atomicAdd(&g_adj[g * 4 + 1], v01);
        atomicAdd(&g_adj[g * 4 + 2], v10);
        atomicAdd(&g_adj[g * 4 + 3], v11);
    }
}

__global__ __launch_bounds__(512) void k_penalty(float* __restrict__ out) {
    __shared__ float red[512];
    int g = threadIdx.x;
    float a00 = g_adj[g * 4], a01 = g_adj[g * 4 + 1];
    float a10 = g_adj[g * 4 + 2], a11 = g_adj[g * 4 + 3];
    float l0 = fmaxf(fabsf(a00) + fabsf(a01), EPSV);
    float l1 = fmaxf(fabsf(a10) + fabsf(a11), EPSV);
    float d0 = a00 / l0 - 1.f, d1 = a11 / l1 - 1.f;
    red[g] = d0 * d0 + d1 * d1;
    __syncthreads();
    for (int o = 256; o; o >>= 1) {
        if (g < o) red[g] += red[g + o];
        __syncthreads();
    }
    if (g == 0) out[OFF_PEN] = red[0] / (2.f * NG);
}

// ---------------- gemb (global mean) ----------------
__global__ __launch_bounds__(512) void k_colsum(const float* __restrict__ h) {
    int c = threadIdx.x;
    int n0 = blockIdx.x * 256;
    float acc = 0.f;
    for (int i = 0; i < 256; i++)
        acc += h[(size_t)(n0 + i) * HIDD + c];
    atomicAdd(&g_colsum[c], acc);
}

__global__ __launch_bounds__(512) void k_gemb() {
    __shared__ float red[512];
    __shared__ float s_s;
    int c = threadIdx.x;
    float m = g_colsum[c] * (1.0f / NN);
    red[c] = m * m;
    __syncthreads();
    for (int o = 256; o; o >>= 1) {
        if (c < o) red[c] += red[c + o];
        __syncthreads();
    }
    if (c == 0) {
        float p = sqrtf(red[0] / HIDD);
        s_s = (p > 1.f) ? 1.f / p : 1.f;
    }
    __syncthreads();
    g_m[c] = m * s_s;
}

__global__ __launch_bounds__(512) void k_bcast(float* __restrict__ out) {
    out[OFF_GEMB + blockIdx.x * HIDD + threadIdx.x] = g_m[threadIdx.x];
}

// ---------------- pos normalization ----------------
__global__ __launch_bounds__(512) void k_sumsq() {
    __shared__ float red[512];
    int i = blockIdx.x * 512 + threadIdx.x;
    float v = g_pos[i];
    red[threadIdx.x] = v * v;
    __syncthreads();
    for (int o = 256; o; o >>= 1) {
        if (threadIdx.x < o) red[threadIdx.x] += red[threadIdx.x + o];
        __syncthreads();
    }
    if (threadIdx.x == 0) atomicAdd(&g_scal[0], red[0]);
}

__global__ __launch_bounds__(512) void k_scale_pos(float* __restrict__ out) {
    int i = blockIdx.x * 512 + threadIdx.x;
    float p = sqrtf(g_scal[0] / (float)(NG * HIDD));
    float s = (p > 1.f) ? 1.f / p : 1.f;
    float v = g_pos[i] * s;
    g_pos[i] = v;
    out[OFF_POS + i] = v;
    __nv_bfloat16 h, l;
    split2(v, h, l);
    g_posh[i] = h;
    g_posl[i] = l;
}

// ---------------- classifier head: one warp per graph ----------------
__global__ void k_head(const float* __restrict__ t2,
                       const float* __restrict__ Wl2,
                       const float* __restrict__ bl2,
                       float* __restrict__ out)
{
    int w = (blockIdx.x * blockDim.x + threadIdx.x) >> 5;
    int lane = threadIdx.x & 31;
    if (w >= NG) return;
    const float* row = t2 + (size_t)w * HIDD;
    float acc[NCLS] = {0, 0, 0, 0, 0, 0};
    for (int k = lane; k < HIDD; k += 32) {
        float v = row[k];
        #pragma unroll
        for (int j = 0; j < NCLS; j++)
            acc[j] += v * Wl2[k * NCLS + j];
    }
    #pragma unroll
    for (int j = 0; j < NCLS; j++)
        #pragma unroll
        for (int o = 16; o; o >>= 1)
            acc[j] += __shfl_down_sync(0xffffffffu, acc[j], o);
    if (lane == 0) {
        float o_[NCLS];
        float m = -1e30f;
        #pragma unroll
        for (int j = 0; j < NCLS; j++) { o_[j] = acc[j] + bl2[j]; m = fmaxf(m, o_[j]); }
        float s = 0.f;
        #pragma unroll
        for (int j = 0; j < NCLS; j++) s += expf(o_[j] - m);
        float lse = logf(s) + m;
        #pragma unroll
        for (int j = 0; j < NCLS; j++)
            out[OFF_LOGP + w * NCLS + j] = o_[j] - lse;
    }
}

// ---------------- launch ----------------
extern "C" void kernel_launch(void* const* d_in, const int* in_sizes, int n_in,
                              void* d_out, int out_size)
{
    const float* x   = (const float*)d_in[0];
    const int*   ei  = (const int*)d_in[1];
    const float* W1  = (const float*)d_in[4];
    const float* b1  = (const float*)d_in[5];
    const float* W2  = (const float*)d_in[6];
    const float* b2  = (const float*)d_in[7];
    const float* W3  = (const float*)d_in[8];
    const float* b3  = (const float*)d_in[9];
    const float* Wc1 = (const float*)d_in[10];
    const float* bc1 = (const float*)d_in[11];
    const float* Wc2 = (const float*)d_in[12];
    const float* bc2 = (const float*)d_in[13];
    const float* Wl1 = (const float*)d_in[14];
    const float* bl1 = (const float*)d_in[15];
    const float* Wl2 = (const float*)d_in[16];
    const float* bl2 = (const float*)d_in[17];
    float* out = (float*)d_out;

    const int* src = ei;
    const int* dst = ei + NE;

    void *pA, *pB, *pPos, *pCnt, *pAdj, *pCol, *pScal;
    void *pAh, *pAl, *pPh, *pPl;
    void *pw1h, *pw1l, *pw2h, *pw2l, *pw3h, *pw3l, *pwc1h, *pwc1l, *pwl1h, *pwl1l;
    cudaGetSymbolAddress(&pA, g_bufA);
    cudaGetSymbolAddress(&pB, g_bufB);
    cudaGetSymbolAddress(&pPos, g_pos);
    cudaGetSymbolAddress(&pCnt, g_cnt);
    cudaGetSymbolAddress(&pAdj, g_adj);
    cudaGetSymbolAddress(&pCol, g_colsum);
    cudaGetSymbolAddress(&pScal, g_scal);
    cudaGetSymbolAddress(&pAh, g_ah);
    cudaGetSymbolAddress(&pAl, g_al);
    cudaGetSymbolAddress(&pPh, g_posh);
    cudaGetSymbolAddress(&pPl, g_posl);
    cudaGetSymbolAddress(&pw1h, g_w1h);  cudaGetSymbolAddress(&pw1l, g_w1l);
    cudaGetSymbolAddress(&pw2h, g_w2h);  cudaGetSymbolAddress(&pw2l, g_w2l);
    cudaGetSymbolAddress(&pw3h, g_w3h);  cudaGetSymbolAddress(&pw3l, g_w3l);
    cudaGetSymbolAddress(&pwc1h, g_wc1h); cudaGetSymbolAddress(&pwc1l, g_wc1l);
    cudaGetSymbolAddress(&pwl1h, g_wl1h); cudaGetSymbolAddress(&pwl1l, g_wl1l);

    float* bufA = (float*)pA;
    float* bufB = (float*)pB;
    __nv_bfloat16* ah = (__nv_bfloat16*)pAh;
    __nv_bfloat16* al = (__nv_bfloat16*)pAl;

    cudaFuncSetAttribute(k_agg, cudaFuncAttributeMaxDynamicSharedMemorySize,
                         NPG * HIDD * (int)sizeof(float));

    cudaMemsetAsync(pCnt, 0, NN * sizeof(int));
    cudaMemsetAsync(pAdj, 0, NG * 4 * sizeof(float));
    cudaMemsetAsync(pCol, 0, HIDD * sizeof(float));
    cudaMemsetAsync(pScal, 0, 4 * sizeof(float));

    // CSR build + degree norm
    k_count<<<NE / 256, 256>>>(dst);
    k_scan<<<2, 256>>>();
    k_fill<<<NE / 256, 256>>>(src, dst);

    // conversions
    k_cvt_x<<<NN * FIN / 256, 256>>>(x);
    k_cvt_w<<<HIDD * FIN / 256, 256>>>(W1, (__nv_bfloat16*)pw1h, (__nv_bfloat16*)pw1l, FIN);
    k_cvt_w<<<HIDD * HIDD / 256, 256>>>(W2, (__nv_bfloat16*)pw2h, (__nv_bfloat16*)pw2l, HIDD);
    k_cvt_w<<<HIDD * HIDD / 256, 256>>>(W3, (__nv_bfloat16*)pw3h, (__nv_bfloat16*)pw3l, HIDD);
    k_cvt_w<<<HIDD * HIDD / 256, 256>>>(Wc1, (__nv_bfloat16*)pwc1h, (__nv_bfloat16*)pwc1l, HIDD);
    k_cvt_w<<<HIDD * HIDD / 256, 256>>>(Wl1, (__nv_bfloat16*)pwl1h, (__nv_bfloat16*)pwl1l, HIDD);

    const int SMEM_AGG = NPG * HIDD * (int)sizeof(float);
    dim3 gbig(NN / 128, HIDD / 128);     // (400, 4)
    dim3 gsmall(NG / 128, HIDD / 128);   // (4, 4)

    // 3 GCN layers (mma.sync GEMM + smem aggregation)
    tgemm<<<gbig, 256>>>(ah, al, FIN,
        (__nv_bfloat16*)pw1h, (__nv_bfloat16*)pw1l, nullptr, bufB, FIN, 0);
    k_agg<<<NG, 512, SMEM_AGG>>>(bufB, b1, bufA, ah, al);
    tgemm<<<gbig, 256>>>(ah, al, HIDD,
        (__nv_bfloat16*)pw2h, (__nv_bfloat16*)pw2l, nullptr, bufB, HIDD, 0);
    k_agg<<<NG, 512, SMEM_AGG>>>(bufB, b2, bufA, ah, al);
    tgemm<<<gbig, 256>>>(ah, al, HIDD,
        (__nv_bfloat16*)pw3h, (__nv_bfloat16*)pw3l, nullptr, bufB, HIDD, 0);
    k_agg<<<NG, 512, SMEM_AGG>>>(bufB, b3, bufA, ah, al);   // bufA = h3

    // assignment = softmax(tanh(h3@Wc1+bc1)@Wc2+bc2)
    tgemm<<<gbig, 256>>>(ah, al, HIDD,
        (__nv_bfloat16*)pwc1h, (__nv_bfloat16*)pwc1l, bc1, bufB, HIDD, 1);
    k_assign<<<NN / 8, 256>>>(bufB, Wc2, bc2);

    // pooled pos, adjacency penalty, gemb
    k_pos<<<NG, 512>>>(bufA);
    k_adj<<<NE / 256, 256>>>(src, dst);
    k_penalty<<<1, 512>>>(out);
    k_colsum<<<NN / 256, 512>>>(bufA);
    k_gemb<<<1, 512>>>();
    k_bcast<<<NG, 512>>>(out);

    // pos power-normalization (also emits pos hi/lo)
    k_sumsq<<<NG * HIDD / 512, 512>>>();
    k_scale_pos<<<NG * HIDD / 512, 512>>>(out);

    // classifier
    tgemm<<<gsmall, 256>>>((__nv_bfloat16*)pPh, (__nv_bfloat16*)pPl, HIDD,
        (__nv_bfloat16*)pwl1h, (__nv_bfloat16*)pwl1l, bl1, bufB, HIDD, 2);
    k_head<<<NG / 8, 256>>>(bufB, Wl2, bl2, out);
}